// round 5
// baseline (speedup 1.0000x reference)
#include <cuda_runtime.h>
#include <cstdint>

#define RR 10
#define BLOCK 128

typedef unsigned long long ull;

// S table: [k=u/2][a][a2] as float2 = (S[2k,a,a2], S[2k+1,a,a2])
__device__ __align__(16) float2 S2g[16 * 16 * 16];

// ---------------------------------------------------------------------------
// Precompute kernel: one block per unit u (32 blocks, 256 threads).
// ---------------------------------------------------------------------------
__global__ void precompute_S(const float* __restrict__ core11,
                             const float* __restrict__ core12,
                             const float* __restrict__ core13,
                             const float* __restrict__ core14,
                             const float* __restrict__ core21,
                             const float* __restrict__ core22,
                             const float* __restrict__ FM,   // [2][10][8][32]
                             const float* __restrict__ MT)   // [10][10]
{
    __shared__ float v[8][2][RR];
    __shared__ float WP[4][2][RR][RR];
    __shared__ float P[4][4][RR];
    __shared__ float W2[2][4][RR][RR];
    __shared__ float Q[2][16][RR];
    __shared__ float QT[16][RR];

    const int u = blockIdx.x;
    const int tid = threadIdx.x;

    for (int idx = tid; idx < 8 * 2 * RR; idx += blockDim.x) {
        int f = idx / (2 * RR);
        int d = (idx / RR) & 1;
        int r = idx % RR;
        v[f][d][r] = FM[((d * RR + r) * 8 + f) * 32 + u];
    }
    __syncthreads();

    const float* cores1[4] = {core11, core12, core13, core14};

    for (int idx = tid; idx < 800; idx += blockDim.x) {
        int p  = idx / 200;
        int al = (idx / 100) & 1;
        int k  = (idx / RR) % RR;
        int j  = idx % RR;
        const float* core = cores1[p];
        float s = 0.f;
        #pragma unroll
        for (int i = 0; i < RR; i++)
            s += v[2 * p][al][i] * __ldg(&core[(i * RR + k) * RR + j]);
        WP[p][al][k][j] = s;
    }
    __syncthreads();

    for (int idx = tid; idx < 160; idx += blockDim.x) {
        int p = idx / 40;
        int c = (idx / RR) & 3;
        int j = idx % RR;
        int al = c >> 1, be = c & 1;
        float s = 0.f;
        #pragma unroll
        for (int k = 0; k < RR; k++)
            s += v[2 * p + 1][be][k] * WP[p][al][k][j];
        P[p][c][j] = s;
    }
    __syncthreads();

    for (int idx = tid; idx < 800; idx += blockDim.x) {
        int t  = idx / 400;
        int c1 = (idx / 100) & 3;
        int k  = (idx / RR) % RR;
        int j  = idx % RR;
        const float* core = t ? core22 : core21;
        float s = 0.f;
        #pragma unroll
        for (int i = 0; i < RR; i++)
            s += P[2 * t][c1][i] * __ldg(&core[(i * RR + k) * RR + j]);
        W2[t][c1][k][j] = s;
    }
    __syncthreads();

    for (int idx = tid; idx < 320; idx += blockDim.x) {
        int t = idx / 160;
        int a = (idx / RR) % 16;
        int j = idx % RR;
        int c1 = a >> 2, c2 = a & 3;
        float s = 0.f;
        #pragma unroll
        for (int k = 0; k < RR; k++)
            s += P[2 * t + 1][c2][k] * W2[t][c1][k][j];
        Q[t][a][j] = s;
    }
    __syncthreads();

    for (int idx = tid; idx < 160; idx += blockDim.x) {
        int a = idx / RR, j = idx % RR;
        float s = 0.f;
        #pragma unroll
        for (int i = 0; i < RR; i++)
            s += Q[0][a][i] * __ldg(&MT[i * RR + j]);
        QT[a][j] = s;
    }
    __syncthreads();

    for (int idx = tid; idx < 256; idx += blockDim.x) {
        int a = idx >> 4, a2 = idx & 15;
        float s = 0.f;
        #pragma unroll
        for (int j = 0; j < RR; j++)
            s += QT[a][j] * Q[1][a2][j];
        float* dst = reinterpret_cast<float*>(&S2g[((u >> 1) * 16 + a) * 16 + a2]);
        dst[u & 1] = s;
    }
}

// ---------------------------------------------------------------------------
// f32x2 helpers
// ---------------------------------------------------------------------------
__device__ __forceinline__ ull pack2(float lo, float hi) {
    ull r;
    asm("mov.b64 %0, {%1, %2};" : "=l"(r) : "f"(lo), "f"(hi));
    return r;
}
__device__ __forceinline__ ull fma2(ull a, ull b, ull c) {
    ull d;
    asm("fma.rn.f32x2 %0, %1, %2, %3;" : "=l"(d) : "l"(a), "l"(b), "l"(c));
    return d;
}

// ---------------------------------------------------------------------------
// Main kernel: thread = 4 batches x ONE u-pair (2 units), a2 split in 2 passes.
// Each S ulonglong2 (2 a2-columns) feeds 8 FMA2 (2 a2 x 4 batches).
// Block = 128 threads on same u-pair -> 2KB S slice in smem.
// Grid = (B/512) * 16.
// ---------------------------------------------------------------------------
__global__ __launch_bounds__(BLOCK, 3) void tree_main(const float* __restrict__ X,
                                                      float* __restrict__ out)
{
    __shared__ __align__(16) ulonglong2 sS[128];   // 2KB: [a=0..15][q=0..7]

    const int kg   = blockIdx.x & 15;       // u-pair index (units 2kg, 2kg+1)
    const int bblk = blockIdx.x >> 4;

    {   // stage this u-pair's S slice: 256 float2 = 2KB
        const ulonglong2* src = reinterpret_cast<const ulonglong2*>(S2g) + kg * 128;
        sS[threadIdx.x] = src[threadIdx.x];
    }
    __syncthreads();

    // ---- load X for 4 batches, build rank-1 monomial factors ----
    int   bidx[4];
    float M01[4][4], M23[4][4], M45[4][4], M67[4][4];
    #pragma unroll
    for (int i = 0; i < 4; i++) {
        int bb = bblk * (4 * BLOCK) + i * BLOCK + threadIdx.x;
        bidx[i] = bb;
        const float4* xp = reinterpret_cast<const float4*>(X + (size_t)bb * 16);
        float4 x0 = xp[0], x1 = xp[1], x2 = xp[2], x3 = xp[3];
        M01[i][0] = x0.x * x0.z; M01[i][1] = x0.x * x0.w;
        M01[i][2] = x0.y * x0.z; M01[i][3] = x0.y * x0.w;
        M23[i][0] = x1.x * x1.z; M23[i][1] = x1.x * x1.w;
        M23[i][2] = x1.y * x1.z; M23[i][3] = x1.y * x1.w;
        M45[i][0] = x2.x * x2.z; M45[i][1] = x2.x * x2.w;
        M45[i][2] = x2.y * x2.z; M45[i][3] = x2.y * x2.w;
        M67[i][0] = x3.x * x3.z; M67[i][1] = x3.x * x3.w;
        M67[i][2] = x3.y * x3.z; M67[i][3] = x3.y * x3.w;
    }

    ull acc0 = 0ull, acc1 = 0ull, acc2 = 0ull, acc3 = 0ull;

    #pragma unroll
    for (int h = 0; h < 2; h++) {
        // mon2 duplicated-packs for a2 in [8h, 8h+8): j -> a2 = 8h + j
        ull md[4][8];
        #pragma unroll
        for (int i = 0; i < 4; i++)
            #pragma unroll
            for (int j = 0; j < 8; j++) {
                float v = M45[i][2 * h + (j >> 2)] * M67[i][j & 3];
                md[i][j] = pack2(v, v);
            }

        #pragma unroll 4
        for (int a = 0; a < 16; a++) {
            ull t0 = 0ull, t1 = 0ull, t2 = 0ull, t3 = 0ull;
            const ulonglong2* row = sS + a * 8 + 4 * h;
            #pragma unroll
            for (int q = 0; q < 4; q++) {
                ulonglong2 s = row[q];
                t0 = fma2(s.x, md[0][2 * q], t0); t0 = fma2(s.y, md[0][2 * q + 1], t0);
                t1 = fma2(s.x, md[1][2 * q], t1); t1 = fma2(s.y, md[1][2 * q + 1], t1);
                t2 = fma2(s.x, md[2][2 * q], t2); t2 = fma2(s.y, md[2][2 * q + 1], t2);
                t3 = fma2(s.x, md[3][2 * q], t3); t3 = fma2(s.y, md[3][2 * q + 1], t3);
            }
            float m1;
            m1 = M01[0][a >> 2] * M23[0][a & 3]; acc0 = fma2(t0, pack2(m1, m1), acc0);
            m1 = M01[1][a >> 2] * M23[1][a & 3]; acc1 = fma2(t1, pack2(m1, m1), acc1);
            m1 = M01[2][a >> 2] * M23[2][a & 3]; acc2 = fma2(t2, pack2(m1, m1), acc2);
            m1 = M01[3][a >> 2] * M23[3][a & 3]; acc3 = fma2(t3, pack2(m1, m1), acc3);
        }
    }

    // out[b, 2kg .. 2kg+1] : one 8B store per batch
    *reinterpret_cast<ull*>(out + (size_t)bidx[0] * 32 + kg * 2) = acc0;
    *reinterpret_cast<ull*>(out + (size_t)bidx[1] * 32 + kg * 2) = acc1;
    *reinterpret_cast<ull*>(out + (size_t)bidx[2] * 32 + kg * 2) = acc2;
    *reinterpret_cast<ull*>(out + (size_t)bidx[3] * 32 + kg * 2) = acc3;
}

// ---------------------------------------------------------------------------
extern "C" void kernel_launch(void* const* d_in, const int* in_sizes, int n_in,
                              void* d_out, int out_size)
{
    const float* X   = (const float*)d_in[0];
    const float* c11 = (const float*)d_in[1];
    const float* c12 = (const float*)d_in[2];
    const float* c13 = (const float*)d_in[3];
    const float* c14 = (const float*)d_in[4];
    const float* c21 = (const float*)d_in[5];
    const float* c22 = (const float*)d_in[6];
    const float* FM  = (const float*)d_in[7];
    const float* MT  = (const float*)d_in[8];
    (void)n_in; (void)out_size;

    int B = in_sizes[0] / 16;          // X is [B, 8, 2]
    int nbblk = B / (4 * BLOCK);       // 128 for B=65536

    precompute_S<<<32, 256>>>(c11, c12, c13, c14, c21, c22, FM, MT);
    tree_main<<<nbblk * 16, BLOCK>>>(X, (float*)d_out);
}

// round 7
// speedup vs baseline: 1.1872x; 1.1872x over previous
#include <cuda_runtime.h>
#include <cuda_bf16.h>
#include <cstdint>

typedef unsigned long long ull;
typedef unsigned int       u32;
typedef unsigned short     u16;

#define RR 10

// Split bilinear-form matrices W[u][k], k = a*16 + a2, bf16 hi/lo parts.
// W[k][u] == Whi_g[u*256 + k] (+ lo part).
__device__ u16 Whi_g[32 * 256];
__device__ u16 Wlo_g[32 * 256];

// ---------------------------------------------------------------------------
// Precompute kernel: one block per unit u. Builds W[u][k]=S[u][a][a2], split bf16.
// ---------------------------------------------------------------------------
__global__ void precompute_S(const float* __restrict__ core11,
                             const float* __restrict__ core12,
                             const float* __restrict__ core13,
                             const float* __restrict__ core14,
                             const float* __restrict__ core21,
                             const float* __restrict__ core22,
                             const float* __restrict__ FM,   // [2][10][8][32]
                             const float* __restrict__ MT)   // [10][10]
{
    __shared__ float v[8][2][RR];
    __shared__ float WP[4][2][RR][RR];
    __shared__ float P[4][4][RR];
    __shared__ float W2[2][4][RR][RR];
    __shared__ float Q[2][16][RR];
    __shared__ float QT[16][RR];

    const int u = blockIdx.x;
    const int tid = threadIdx.x;

    for (int idx = tid; idx < 8 * 2 * RR; idx += blockDim.x) {
        int f = idx / (2 * RR);
        int d = (idx / RR) & 1;
        int r = idx % RR;
        v[f][d][r] = FM[((d * RR + r) * 8 + f) * 32 + u];
    }
    __syncthreads();

    const float* cores1[4] = {core11, core12, core13, core14};

    for (int idx = tid; idx < 800; idx += blockDim.x) {
        int p  = idx / 200;
        int al = (idx / 100) & 1;
        int k  = (idx / RR) % RR;
        int j  = idx % RR;
        const float* core = cores1[p];
        float s = 0.f;
        #pragma unroll
        for (int i = 0; i < RR; i++)
            s += v[2 * p][al][i] * __ldg(&core[(i * RR + k) * RR + j]);
        WP[p][al][k][j] = s;
    }
    __syncthreads();

    for (int idx = tid; idx < 160; idx += blockDim.x) {
        int p = idx / 40;
        int c = (idx / RR) & 3;
        int j = idx % RR;
        int al = c >> 1, be = c & 1;
        float s = 0.f;
        #pragma unroll
        for (int k = 0; k < RR; k++)
            s += v[2 * p + 1][be][k] * WP[p][al][k][j];
        P[p][c][j] = s;
    }
    __syncthreads();

    for (int idx = tid; idx < 800; idx += blockDim.x) {
        int t  = idx / 400;
        int c1 = (idx / 100) & 3;
        int k  = (idx / RR) % RR;
        int j  = idx % RR;
        const float* core = t ? core22 : core21;
        float s = 0.f;
        #pragma unroll
        for (int i = 0; i < RR; i++)
            s += P[2 * t][c1][i] * __ldg(&core[(i * RR + k) * RR + j]);
        W2[t][c1][k][j] = s;
    }
    __syncthreads();

    for (int idx = tid; idx < 320; idx += blockDim.x) {
        int t = idx / 160;
        int a = (idx / RR) % 16;
        int j = idx % RR;
        int c1 = a >> 2, c2 = a & 3;
        float s = 0.f;
        #pragma unroll
        for (int k = 0; k < RR; k++)
            s += P[2 * t + 1][c2][k] * W2[t][c1][k][j];
        Q[t][a][j] = s;
    }
    __syncthreads();

    for (int idx = tid; idx < 160; idx += blockDim.x) {
        int a = idx / RR, j = idx % RR;
        float s = 0.f;
        #pragma unroll
        for (int i = 0; i < RR; i++)
            s += Q[0][a][i] * __ldg(&MT[i * RR + j]);
        QT[a][j] = s;
    }
    __syncthreads();

    for (int idx = tid; idx < 256; idx += blockDim.x) {
        int a = idx >> 4, a2 = idx & 15;
        float s = 0.f;
        #pragma unroll
        for (int j = 0; j < RR; j++)
            s += QT[a][j] * Q[1][a2][j];
        // split: hi = truncate-to-bf16 (exact), lo = rn-bf16 of residual
        u32 bits = __float_as_uint(s);
        float hif = __uint_as_float(bits & 0xFFFF0000u);
        __nv_bfloat16 lo = __float2bfloat16(s - hif);
        int k = a * 16 + a2;
        Whi_g[u * 256 + k] = (u16)(bits >> 16);
        Wlo_g[u * 256 + k] = *reinterpret_cast<u16*>(&lo);
    }
}

// ---------------------------------------------------------------------------
// Warp-MMA helpers (arch-agnostic: sm_80+ mma.sync / ldmatrix)
// ---------------------------------------------------------------------------
__device__ __forceinline__ u32 smem_u32(const void* p) {
    u32 a;
    asm("{ .reg .u64 t; cvta.to.shared.u64 t, %1; cvt.u32.u64 %0, t; }"
        : "=r"(a) : "l"(p));
    return a;
}
__device__ __forceinline__ void ldm_x4(u32* r, u32 addr) {
    asm volatile("ldmatrix.sync.aligned.m8n8.x4.shared.b16 {%0,%1,%2,%3}, [%4];"
                 : "=r"(r[0]), "=r"(r[1]), "=r"(r[2]), "=r"(r[3]) : "r"(addr));
}
__device__ __forceinline__ void mma_bf16(float* d, const u32* a, u32 b0, u32 b1) {
    asm volatile("mma.sync.aligned.m16n8k16.row.col.f32.bf16.bf16.f32 "
                 "{%0,%1,%2,%3}, {%4,%5,%6,%7}, {%8,%9}, {%0,%1,%2,%3};"
                 : "+f"(d[0]), "+f"(d[1]), "+f"(d[2]), "+f"(d[3])
                 : "r"(a[0]), "r"(a[1]), "r"(a[2]), "r"(a[3]), "r"(b0), "r"(b1));
}

// z row stride in the per-warp staging buffer: 64 bf16 data + 8 pad = 144 bytes.
#define ZSTRIDE 144
#define ZWARP   (16 * 72)         // u16 elements per warp buffer

// ---------------------------------------------------------------------------
// Main kernel: out = z @ W.  Block = 256 thr (8 warps), warp = 16-batch tile.
// 3-term bf16-split MMA: zh*Wh + zh*Wl + zl*Wh, fp32 accumulate.
// Dynamic smem: BH[2048] ull | BL[2048] ull | ZH[8][1152] u16 | ZL[8][1152] u16
// ---------------------------------------------------------------------------
__global__ __launch_bounds__(256) void tree_main(const float* __restrict__ X,
                                                 float* __restrict__ out)
{
    extern __shared__ __align__(16) char dsm[];
    ull* sBH = reinterpret_cast<ull*>(dsm);
    ull* sBL = sBH + 2048;
    u16* sZH = reinterpret_cast<u16*>(sBL + 2048);
    u16* sZL = sZH + 8 * ZWARP;

    const int tid  = threadIdx.x;
    const int wid  = tid >> 5;
    const int lane = tid & 31;

    // ---- stage B fragments (per-lane layout for mma.sync m16n8k16) ----
    // entry e = ksglobal*128 + n*32 + lane; lane: tig=lane&3, gid=lane>>2
    // b0 = {W[k0][col], W[k0+1][col]}, b1 = {W[k0+8][col], W[k0+9][col]}
    for (int e = tid; e < 2048; e += 256) {
        int l   = e & 31;
        int n   = (e >> 5) & 3;
        int ks  = e >> 7;
        int col = n * 8 + (l >> 2);
        int k0  = ks * 16 + (l & 3) * 2;
        const u16* wh = &Whi_g[col * 256];
        const u16* wl = &Wlo_g[col * 256];
        sBH[e] = (ull)wh[k0] | ((ull)wh[k0 + 1] << 16)
               | ((ull)wh[k0 + 8] << 32) | ((ull)wh[k0 + 9] << 48);
        sBL[e] = (ull)wl[k0] | ((ull)wl[k0 + 1] << 16)
               | ((ull)wl[k0 + 8] << 32) | ((ull)wl[k0 + 9] << 48);
    }
    __syncthreads();

    const int base_b = (blockIdx.x * 8 + wid) * 16;
    const int zrow   = lane >> 1;          // z-build row (0..15), 2 lanes per row

    // ---- monomials for this lane's z-build row ----
    const float4* xp = reinterpret_cast<const float4*>(X + (size_t)(base_b + zrow) * 16);
    float4 x0 = xp[0], x1 = xp[1], x2 = xp[2], x3 = xp[3];

    float a01[4], a23[4], a45[4], a67[4];
    a01[0]=x0.x*x0.z; a01[1]=x0.x*x0.w; a01[2]=x0.y*x0.z; a01[3]=x0.y*x0.w;
    a23[0]=x1.x*x1.z; a23[1]=x1.x*x1.w; a23[2]=x1.y*x1.z; a23[3]=x1.y*x1.w;
    a45[0]=x2.x*x2.z; a45[1]=x2.x*x2.w; a45[2]=x2.y*x2.z; a45[3]=x2.y*x2.w;
    a67[0]=x3.x*x3.z; a67[1]=x3.x*x3.w; a67[2]=x3.y*x3.z; a67[3]=x3.y*x3.w;

    float m1[16], m2[16];
    #pragma unroll
    for (int c1 = 0; c1 < 4; c1++)
        #pragma unroll
        for (int c2 = 0; c2 < 4; c2++) {
            m1[c1 * 4 + c2] = a01[c1] * a23[c2];
            m2[c1 * 4 + c2] = a45[c1] * a67[c2];
        }

    char* zh = (char*)(sZH + wid * ZWARP);
    char* zl = (char*)(sZL + wid * ZWARP);

    // ldmatrix per-lane source address (x4: rows 0-15, +16B for lanes 16-31)
    const u32 zh_base = smem_u32(zh);
    const u32 zl_base = smem_u32(zl);
    const u32 aoff = (u32)(lane & 15) * ZSTRIDE + ((lane & 16) ? 16u : 0u);

    float acc[4][4];
    #pragma unroll
    for (int n = 0; n < 4; n++)
        #pragma unroll
        for (int i = 0; i < 4; i++) acc[n][i] = 0.f;

    // ---- 4 K-chunks of 64 ----
    #pragma unroll 1
    for (int c = 0; c < 4; c++) {
        __syncwarp();    // prior chunk's ldmatrix reads done before overwrite

        // build z for a = c*4 + (lane&1)*2 + {0,1}, all a2
        const int ab = c * 4 + (lane & 1) * 2;
        #pragma unroll
        for (int al = 0; al < 2; al++) {
            float ma = m1[ab + al];
            u32 hi[8], lo[8];
            #pragma unroll
            for (int p = 0; p < 8; p++) {
                float z0 = ma * m2[2 * p];
                float z1 = ma * m2[2 * p + 1];
                u32 u0 = __float_as_uint(z0);
                u32 u1 = __float_as_uint(z1);
                float h0 = __uint_as_float(u0 & 0xFFFF0000u);
                float h1 = __uint_as_float(u1 & 0xFFFF0000u);
                u32 hp;
                asm("prmt.b32 %0, %1, %2, 0x7632;" : "=r"(hp) : "r"(u0), "r"(u1));
                float l0 = z0 - h0, l1 = z1 - h1;
                u32 lp;
                asm("cvt.rn.bf16x2.f32 %0, %1, %2;" : "=r"(lp) : "f"(l1), "f"(l0));
                hi[p] = hp;
                lo[p] = lp;
            }
            u32 off = (u32)zrow * ZSTRIDE + (u32)(lane & 1) * 64 + (u32)al * 32;
            *reinterpret_cast<uint4*>(zh + off)      = make_uint4(hi[0], hi[1], hi[2], hi[3]);
            *reinterpret_cast<uint4*>(zh + off + 16) = make_uint4(hi[4], hi[5], hi[6], hi[7]);
            *reinterpret_cast<uint4*>(zl + off)      = make_uint4(lo[0], lo[1], lo[2], lo[3]);
            *reinterpret_cast<uint4*>(zl + off + 16) = make_uint4(lo[4], lo[5], lo[6], lo[7]);
        }
        __syncwarp();

        // ---- MMA over the 4 k-steps of this chunk ----
        #pragma unroll
        for (int ks = 0; ks < 4; ks++) {
            u32 ah[4], al_[4];
            ldm_x4(ah,  zh_base + aoff + (u32)ks * 32);
            ldm_x4(al_, zl_base + aoff + (u32)ks * 32);
            const int kglob = c * 4 + ks;
            #pragma unroll
            for (int n = 0; n < 4; n++) {
                ull bh = sBH[(kglob * 4 + n) * 32 + lane];
                ull bl = sBL[(kglob * 4 + n) * 32 + lane];
                u32 bh0 = (u32)bh, bh1 = (u32)(bh >> 32);
                u32 bl0 = (u32)bl, bl1 = (u32)(bl >> 32);
                mma_bf16(acc[n], ah,  bh0, bh1);
                mma_bf16(acc[n], ah,  bl0, bl1);
                mma_bf16(acc[n], al_, bh0, bh1);
            }
        }
    }

    // ---- epilogue: D frag (row g / g+8, col tig*2, tig*2+1) ----
    const int g  = lane >> 2;
    const int tg = lane & 3;
    #pragma unroll
    for (int n = 0; n < 4; n++) {
        float2 v0; v0.x = acc[n][0]; v0.y = acc[n][1];
        float2 v1; v1.x = acc[n][2]; v1.y = acc[n][3];
        *reinterpret_cast<float2*>(out + (size_t)(base_b + g)     * 32 + n * 8 + tg * 2) = v0;
        *reinterpret_cast<float2*>(out + (size_t)(base_b + g + 8) * 32 + n * 8 + tg * 2) = v1;
    }
}

#define DSM_BYTES (2048 * 8 * 2 + 8 * ZWARP * 2 * 2)   // 69632

// ---------------------------------------------------------------------------
extern "C" void kernel_launch(void* const* d_in, const int* in_sizes, int n_in,
                              void* d_out, int out_size)
{
    const float* X   = (const float*)d_in[0];
    const float* c11 = (const float*)d_in[1];
    const float* c12 = (const float*)d_in[2];
    const float* c13 = (const float*)d_in[3];
    const float* c14 = (const float*)d_in[4];
    const float* c21 = (const float*)d_in[5];
    const float* c22 = (const float*)d_in[6];
    const float* FM  = (const float*)d_in[7];
    const float* MT  = (const float*)d_in[8];
    (void)n_in; (void)out_size;

    int B = in_sizes[0] / 16;          // X is [B, 8, 2]
    int nblocks = B / 128;             // 8 warps x 16 batches per block

    cudaFuncSetAttribute(tree_main, cudaFuncAttributeMaxDynamicSharedMemorySize,
                         DSM_BYTES);

    precompute_S<<<32, 256>>>(c11, c12, c13, c14, c21, c22, FM, MT);
    tree_main<<<nblocks, 256, DSM_BYTES>>>(X, (float*)d_out);
}

// round 8
// speedup vs baseline: 1.3649x; 1.1497x over previous
#include <cuda_runtime.h>
#include <cuda_bf16.h>
#include <cstdint>

typedef unsigned long long ull;
typedef unsigned int       u32;
typedef unsigned short     u16;

#define RR 10

// Split bilinear-form matrices W[u][k], k = a*16 + a2, bf16 hi/lo parts.
__device__ u16 Whi_g[32 * 256];
__device__ u16 Wlo_g[32 * 256];

// ---------------------------------------------------------------------------
// Precompute kernel: one block per unit u. Builds W[u][k]=S[u][a][a2], split bf16.
// ---------------------------------------------------------------------------
__global__ void precompute_S(const float* __restrict__ core11,
                             const float* __restrict__ core12,
                             const float* __restrict__ core13,
                             const float* __restrict__ core14,
                             const float* __restrict__ core21,
                             const float* __restrict__ core22,
                             const float* __restrict__ FM,   // [2][10][8][32]
                             const float* __restrict__ MT)   // [10][10]
{
    __shared__ float v[8][2][RR];
    __shared__ float WP[4][2][RR][RR];
    __shared__ float P[4][4][RR];
    __shared__ float W2[2][4][RR][RR];
    __shared__ float Q[2][16][RR];
    __shared__ float QT[16][RR];

    const int u = blockIdx.x;
    const int tid = threadIdx.x;

    for (int idx = tid; idx < 8 * 2 * RR; idx += blockDim.x) {
        int f = idx / (2 * RR);
        int d = (idx / RR) & 1;
        int r = idx % RR;
        v[f][d][r] = FM[((d * RR + r) * 8 + f) * 32 + u];
    }
    __syncthreads();

    const float* cores1[4] = {core11, core12, core13, core14};

    for (int idx = tid; idx < 800; idx += blockDim.x) {
        int p  = idx / 200;
        int al = (idx / 100) & 1;
        int k  = (idx / RR) % RR;
        int j  = idx % RR;
        const float* core = cores1[p];
        float s = 0.f;
        #pragma unroll
        for (int i = 0; i < RR; i++)
            s += v[2 * p][al][i] * __ldg(&core[(i * RR + k) * RR + j]);
        WP[p][al][k][j] = s;
    }
    __syncthreads();

    for (int idx = tid; idx < 160; idx += blockDim.x) {
        int p = idx / 40;
        int c = (idx / RR) & 3;
        int j = idx % RR;
        int al = c >> 1, be = c & 1;
        float s = 0.f;
        #pragma unroll
        for (int k = 0; k < RR; k++)
            s += v[2 * p + 1][be][k] * WP[p][al][k][j];
        P[p][c][j] = s;
    }
    __syncthreads();

    for (int idx = tid; idx < 800; idx += blockDim.x) {
        int t  = idx / 400;
        int c1 = (idx / 100) & 3;
        int k  = (idx / RR) % RR;
        int j  = idx % RR;
        const float* core = t ? core22 : core21;
        float s = 0.f;
        #pragma unroll
        for (int i = 0; i < RR; i++)
            s += P[2 * t][c1][i] * __ldg(&core[(i * RR + k) * RR + j]);
        W2[t][c1][k][j] = s;
    }
    __syncthreads();

    for (int idx = tid; idx < 320; idx += blockDim.x) {
        int t = idx / 160;
        int a = (idx / RR) % 16;
        int j = idx % RR;
        int c1 = a >> 2, c2 = a & 3;
        float s = 0.f;
        #pragma unroll
        for (int k = 0; k < RR; k++)
            s += P[2 * t + 1][c2][k] * W2[t][c1][k][j];
        Q[t][a][j] = s;
    }
    __syncthreads();

    for (int idx = tid; idx < 160; idx += blockDim.x) {
        int a = idx / RR, j = idx % RR;
        float s = 0.f;
        #pragma unroll
        for (int i = 0; i < RR; i++)
            s += Q[0][a][i] * __ldg(&MT[i * RR + j]);
        QT[a][j] = s;
    }
    __syncthreads();

    for (int idx = tid; idx < 256; idx += blockDim.x) {
        int a = idx >> 4, a2 = idx & 15;
        float s = 0.f;
        #pragma unroll
        for (int j = 0; j < RR; j++)
            s += QT[a][j] * Q[1][a2][j];
        // split: hi = truncate-to-bf16 (exact), lo = rn-bf16 of residual
        u32 bits = __float_as_uint(s);
        float hif = __uint_as_float(bits & 0xFFFF0000u);
        __nv_bfloat16 lo = __float2bfloat16(s - hif);
        int k = a * 16 + a2;
        Whi_g[u * 256 + k] = (u16)(bits >> 16);
        Wlo_g[u * 256 + k] = *reinterpret_cast<u16*>(&lo);
    }
}

// ---------------------------------------------------------------------------
// Warp-MMA helpers (arch-agnostic: sm_80+ mma.sync)
// ---------------------------------------------------------------------------
__device__ __forceinline__ void mma_bf16(float* d, const u32* a, u32 b0, u32 b1) {
    asm volatile("mma.sync.aligned.m16n8k16.row.col.f32.bf16.bf16.f32 "
                 "{%0,%1,%2,%3}, {%4,%5,%6,%7}, {%8,%9}, {%0,%1,%2,%3};"
                 : "+f"(d[0]), "+f"(d[1]), "+f"(d[2]), "+f"(d[3])
                 : "r"(a[0]), "r"(a[1]), "r"(a[2]), "r"(a[3]), "r"(b0), "r"(b1));
}
// pack high halves of two f32 -> bf16x2 (low half = first arg): exact truncation
__device__ __forceinline__ u32 pack_hi(float z0, float z1) {
    u32 r;
    asm("prmt.b32 %0, %1, %2, 0x7632;"
        : "=r"(r) : "r"(__float_as_uint(z0)), "r"(__float_as_uint(z1)));
    return r;
}
__device__ __forceinline__ u32 pack_lo_rn(float l0, float l1) {
    u32 r;
    asm("cvt.rn.bf16x2.f32 %0, %1, %2;" : "=r"(r) : "f"(l1), "f"(l0));
    return r;
}
__device__ __forceinline__ float trunc_bf(float z) {
    return __uint_as_float(__float_as_uint(z) & 0xFFFF0000u);
}

// ---------------------------------------------------------------------------
// Main kernel: out = z @ W, A-fragments built directly in registers.
// Block = 256 thr (8 warps), warp = 16-batch tile. No Z staging, no ldmatrix.
// 3-term bf16-split: zh*Wh + zh*Wl + zl*Wh, fp32 accumulate.
// ---------------------------------------------------------------------------
__global__ __launch_bounds__(256) void tree_main(const float* __restrict__ X,
                                                 float* __restrict__ out)
{
    __shared__ ull sBH[2048];   // 16KB: B hi fragments, per-lane layout
    __shared__ ull sBL[2048];   // 16KB: B lo fragments

    const int tid  = threadIdx.x;
    const int wid  = tid >> 5;
    const int lane = tid & 31;
    const int g    = lane >> 2;   // fragment row group (0..7)
    const int tig  = lane & 3;    // thread-in-group

    // ---- stage B fragments (same validated layout as round 7) ----
    // entry e: l=e&31, n=(e>>5)&3, ks=e>>7; col=n*8+(l>>2); k0=ks*16+(l&3)*2
    for (int e = tid; e < 2048; e += 256) {
        int l   = e & 31;
        int n   = (e >> 5) & 3;
        int ks  = e >> 7;
        int col = n * 8 + (l >> 2);
        int k0  = ks * 16 + (l & 3) * 2;
        const u16* wh = &Whi_g[col * 256];
        const u16* wl = &Wlo_g[col * 256];
        sBH[e] = (ull)wh[k0] | ((ull)wh[k0 + 1] << 16)
               | ((ull)wh[k0 + 8] << 32) | ((ull)wh[k0 + 9] << 48);
        sBL[e] = (ull)wl[k0] | ((ull)wl[k0 + 1] << 16)
               | ((ull)wl[k0 + 8] << 32) | ((ull)wl[k0 + 9] << 48);
    }
    __syncthreads();

    const int base_b = (blockIdx.x * 8 + wid) * 16;

    // ---- per-lane monomials for its two fragment rows (g, g+8) ----
    // m1r[r][a] for all 16 a; m2r[r][j] for the lane's 4 a2 columns:
    //   a2 = {2tig, 2tig+1, 2tig+8, 2tig+9}
    float m1r[2][16], m2r[2][4];
    #pragma unroll
    for (int r = 0; r < 2; r++) {
        int brow = base_b + g + r * 8;
        const float4* xp = reinterpret_cast<const float4*>(X + (size_t)brow * 16);
        float4 x0 = xp[0], x1 = xp[1], x2 = xp[2], x3 = xp[3];

        float a01[4], a23[4], a45[4], a67[4];
        a01[0]=x0.x*x0.z; a01[1]=x0.x*x0.w; a01[2]=x0.y*x0.z; a01[3]=x0.y*x0.w;
        a23[0]=x1.x*x1.z; a23[1]=x1.x*x1.w; a23[2]=x1.y*x1.z; a23[3]=x1.y*x1.w;
        a45[0]=x2.x*x2.z; a45[1]=x2.x*x2.w; a45[2]=x2.y*x2.z; a45[3]=x2.y*x2.w;
        a67[0]=x3.x*x3.z; a67[1]=x3.x*x3.w; a67[2]=x3.y*x3.z; a67[3]=x3.y*x3.w;

        #pragma unroll
        for (int c1 = 0; c1 < 4; c1++)
            #pragma unroll
            for (int c2 = 0; c2 < 4; c2++)
                m1r[r][c1 * 4 + c2] = a01[c1] * a23[c2];

        #pragma unroll
        for (int j = 0; j < 4; j++) {
            int a2 = 2 * tig + (j >> 1) * 8 + (j & 1);
            m2r[r][j] = a45[a2 >> 2] * a67[a2 & 3];
        }
    }

    float acc[4][4];
    #pragma unroll
    for (int n = 0; n < 4; n++)
        #pragma unroll
        for (int i = 0; i < 4; i++) acc[n][i] = 0.f;

    // ---- 16 K-chunks (each = one 'a' index) ----
    #pragma unroll
    for (int ks = 0; ks < 16; ks++) {
        // z[r][j] = m1[ks] * m2[a2_j]; frag cols: j=0,1 -> k0,k0+1; j=2,3 -> +8
        float z00 = m1r[0][ks] * m2r[0][0], z01 = m1r[0][ks] * m2r[0][1];
        float z02 = m1r[0][ks] * m2r[0][2], z03 = m1r[0][ks] * m2r[0][3];
        float z10 = m1r[1][ks] * m2r[1][0], z11 = m1r[1][ks] * m2r[1][1];
        float z12 = m1r[1][ks] * m2r[1][2], z13 = m1r[1][ks] * m2r[1][3];

        u32 ah[4], al_[4];
        ah[0] = pack_hi(z00, z01);   // row g,   k0..k0+1
        ah[1] = pack_hi(z10, z11);   // row g+8, k0..k0+1
        ah[2] = pack_hi(z02, z03);   // row g,   k0+8..k0+9
        ah[3] = pack_hi(z12, z13);   // row g+8
        al_[0] = pack_lo_rn(z00 - trunc_bf(z00), z01 - trunc_bf(z01));
        al_[1] = pack_lo_rn(z10 - trunc_bf(z10), z11 - trunc_bf(z11));
        al_[2] = pack_lo_rn(z02 - trunc_bf(z02), z03 - trunc_bf(z03));
        al_[3] = pack_lo_rn(z12 - trunc_bf(z12), z13 - trunc_bf(z13));

        // B fragments for the 4 n-tiles
        u32 bh0[4], bh1[4], bl0[4], bl1[4];
        #pragma unroll
        for (int n = 0; n < 4; n++) {
            ull bh = sBH[(ks * 4 + n) * 32 + lane];
            ull bl = sBL[(ks * 4 + n) * 32 + lane];
            bh0[n] = (u32)bh; bh1[n] = (u32)(bh >> 32);
            bl0[n] = (u32)bl; bl1[n] = (u32)(bl >> 32);
        }

        // term-major: dependency chain distance 4
        #pragma unroll
        for (int n = 0; n < 4; n++) mma_bf16(acc[n], ah,  bh0[n], bh1[n]);
        #pragma unroll
        for (int n = 0; n < 4; n++) mma_bf16(acc[n], ah,  bl0[n], bl1[n]);
        #pragma unroll
        for (int n = 0; n < 4; n++) mma_bf16(acc[n], al_, bh0[n], bh1[n]);
    }

    // ---- epilogue: D frag rows g/g+8, cols n*8 + tig*2, +1 ----
    #pragma unroll
    for (int n = 0; n < 4; n++) {
        float2 v0; v0.x = acc[n][0]; v0.y = acc[n][1];
        float2 v1; v1.x = acc[n][2]; v1.y = acc[n][3];
        *reinterpret_cast<float2*>(out + (size_t)(base_b + g)     * 32 + n * 8 + tig * 2) = v0;
        *reinterpret_cast<float2*>(out + (size_t)(base_b + g + 8) * 32 + n * 8 + tig * 2) = v1;
    }
}

// ---------------------------------------------------------------------------
extern "C" void kernel_launch(void* const* d_in, const int* in_sizes, int n_in,
                              void* d_out, int out_size)
{
    const float* X   = (const float*)d_in[0];
    const float* c11 = (const float*)d_in[1];
    const float* c12 = (const float*)d_in[2];
    const float* c13 = (const float*)d_in[3];
    const float* c14 = (const float*)d_in[4];
    const float* c21 = (const float*)d_in[5];
    const float* c22 = (const float*)d_in[6];
    const float* FM  = (const float*)d_in[7];
    const float* MT  = (const float*)d_in[8];
    (void)n_in; (void)out_size;

    int B = in_sizes[0] / 16;          // X is [B, 8, 2]
    int nblocks = B / 128;             // 8 warps x 16 batches per block

    precompute_S<<<32, 256>>>(c11, c12, c13, c14, c21, c22, FM, MT);
    tree_main<<<nblocks, 256>>>(X, (float*)d_out);
}

// round 9
// speedup vs baseline: 1.3993x; 1.0252x over previous
#include <cuda_runtime.h>
#include <cuda_bf16.h>
#include <cstdint>

typedef unsigned long long ull;
typedef unsigned int       u32;
typedef unsigned short     u16;

#define RR 10

// Split bilinear-form matrices W[u][k], k = a*16 + a2, bf16 hi/lo parts.
__device__ u16 Whi_g[32 * 256];
__device__ u16 Wlo_g[32 * 256];
__device__ u32 g_ticket;

// ---------------------------------------------------------------------------
// Precompute kernel: one block per unit u. Builds W[u][k]=S[u][a][a2], split bf16.
// ---------------------------------------------------------------------------
__global__ void precompute_S(const float* __restrict__ core11,
                             const float* __restrict__ core12,
                             const float* __restrict__ core13,
                             const float* __restrict__ core14,
                             const float* __restrict__ core21,
                             const float* __restrict__ core22,
                             const float* __restrict__ FM,   // [2][10][8][32]
                             const float* __restrict__ MT)   // [10][10]
{
    __shared__ float v[8][2][RR];
    __shared__ float WP[4][2][RR][RR];
    __shared__ float P[4][4][RR];
    __shared__ float W2[2][4][RR][RR];
    __shared__ float Q[2][16][RR];
    __shared__ float QT[16][RR];

    const int u = blockIdx.x;
    const int tid = threadIdx.x;

    if (u == 0 && tid == 0) g_ticket = 0u;   // reset warp ticket for tree_main

    for (int idx = tid; idx < 8 * 2 * RR; idx += blockDim.x) {
        int f = idx / (2 * RR);
        int d = (idx / RR) & 1;
        int r = idx % RR;
        v[f][d][r] = FM[((d * RR + r) * 8 + f) * 32 + u];
    }
    __syncthreads();

    const float* cores1[4] = {core11, core12, core13, core14};

    for (int idx = tid; idx < 800; idx += blockDim.x) {
        int p  = idx / 200;
        int al = (idx / 100) & 1;
        int k  = (idx / RR) % RR;
        int j  = idx % RR;
        const float* core = cores1[p];
        float s = 0.f;
        #pragma unroll
        for (int i = 0; i < RR; i++)
            s += v[2 * p][al][i] * __ldg(&core[(i * RR + k) * RR + j]);
        WP[p][al][k][j] = s;
    }
    __syncthreads();

    for (int idx = tid; idx < 160; idx += blockDim.x) {
        int p = idx / 40;
        int c = (idx / RR) & 3;
        int j = idx % RR;
        int al = c >> 1, be = c & 1;
        float s = 0.f;
        #pragma unroll
        for (int k = 0; k < RR; k++)
            s += v[2 * p + 1][be][k] * WP[p][al][k][j];
        P[p][c][j] = s;
    }
    __syncthreads();

    for (int idx = tid; idx < 800; idx += blockDim.x) {
        int t  = idx / 400;
        int c1 = (idx / 100) & 3;
        int k  = (idx / RR) % RR;
        int j  = idx % RR;
        const float* core = t ? core22 : core21;
        float s = 0.f;
        #pragma unroll
        for (int i = 0; i < RR; i++)
            s += P[2 * t][c1][i] * __ldg(&core[(i * RR + k) * RR + j]);
        W2[t][c1][k][j] = s;
    }
    __syncthreads();

    for (int idx = tid; idx < 320; idx += blockDim.x) {
        int t = idx / 160;
        int a = (idx / RR) % 16;
        int j = idx % RR;
        int c1 = a >> 2, c2 = a & 3;
        float s = 0.f;
        #pragma unroll
        for (int k = 0; k < RR; k++)
            s += P[2 * t + 1][c2][k] * W2[t][c1][k][j];
        Q[t][a][j] = s;
    }
    __syncthreads();

    for (int idx = tid; idx < 160; idx += blockDim.x) {
        int a = idx / RR, j = idx % RR;
        float s = 0.f;
        #pragma unroll
        for (int i = 0; i < RR; i++)
            s += Q[0][a][i] * __ldg(&MT[i * RR + j]);
        QT[a][j] = s;
    }
    __syncthreads();

    for (int idx = tid; idx < 256; idx += blockDim.x) {
        int a = idx >> 4, a2 = idx & 15;
        float s = 0.f;
        #pragma unroll
        for (int j = 0; j < RR; j++)
            s += QT[a][j] * Q[1][a2][j];
        // split: hi = truncate-to-bf16 (exact), lo = rn-bf16 of residual
        u32 bits = __float_as_uint(s);
        float hif = __uint_as_float(bits & 0xFFFF0000u);
        __nv_bfloat16 lo = __float2bfloat16(s - hif);
        int k = a * 16 + a2;
        Whi_g[u * 256 + k] = (u16)(bits >> 16);
        Wlo_g[u * 256 + k] = *reinterpret_cast<u16*>(&lo);
    }
}

// ---------------------------------------------------------------------------
// Warp-MMA helpers (arch-agnostic: sm_80+ mma.sync)
// ---------------------------------------------------------------------------
__device__ __forceinline__ void mma_bf16(float* d, const u32* a, u32 b0, u32 b1) {
    asm volatile("mma.sync.aligned.m16n8k16.row.col.f32.bf16.bf16.f32 "
                 "{%0,%1,%2,%3}, {%4,%5,%6,%7}, {%8,%9}, {%0,%1,%2,%3};"
                 : "+f"(d[0]), "+f"(d[1]), "+f"(d[2]), "+f"(d[3])
                 : "r"(a[0]), "r"(a[1]), "r"(a[2]), "r"(a[3]), "r"(b0), "r"(b1));
}
__device__ __forceinline__ u32 pack_hi(float z0, float z1) {
    u32 r;
    asm("prmt.b32 %0, %1, %2, 0x7632;"
        : "=r"(r) : "r"(__float_as_uint(z0)), "r"(__float_as_uint(z1)));
    return r;
}
__device__ __forceinline__ u32 pack_lo_rn(float l0, float l1) {
    u32 r;
    asm("cvt.rn.bf16x2.f32 %0, %1, %2;" : "=r"(r) : "f"(l1), "f"(l0));
    return r;
}
__device__ __forceinline__ float trunc_bf(float z) {
    return __uint_as_float(__float_as_uint(z) & 0xFFFF0000u);
}

// ---------------------------------------------------------------------------
// Main kernel: out = z @ W, A-fragments built in registers, per-warp dynamic
// tickets over 16-batch micro-tiles. Persistent 296 blocks x 256 thr.
// B fragments fused (hi,lo) -> one LDS.128 per (ks, n).
// ---------------------------------------------------------------------------
__global__ __launch_bounds__(256, 3) void tree_main(const float* __restrict__ X,
                                                    float* __restrict__ out,
                                                    int ntiles)
{
    __shared__ __align__(16) ulonglong2 sB[2048];   // 32KB: [ks][n][lane] = {bh, bl}

    const int tid  = threadIdx.x;
    const int lane = tid & 31;
    const int g    = lane >> 2;   // fragment row group (0..7)
    const int tig  = lane & 3;    // thread-in-group

    // ---- stage fused B fragments (validated per-lane layout) ----
    for (int e = tid; e < 2048; e += 256) {
        int l   = e & 31;
        int n   = (e >> 5) & 3;
        int ks  = e >> 7;
        int col = n * 8 + (l >> 2);
        int k0  = ks * 16 + (l & 3) * 2;
        const u16* wh = &Whi_g[col * 256];
        const u16* wl = &Wlo_g[col * 256];
        ull bh = (ull)wh[k0] | ((ull)wh[k0 + 1] << 16)
               | ((ull)wh[k0 + 8] << 32) | ((ull)wh[k0 + 9] << 48);
        ull bl = (ull)wl[k0] | ((ull)wl[k0 + 1] << 16)
               | ((ull)wl[k0 + 8] << 32) | ((ull)wl[k0 + 9] << 48);
        ulonglong2 p; p.x = bh; p.y = bl;
        sB[e] = p;
    }
    __syncthreads();

    // ---- per-warp ticket loop over 16-batch micro-tiles ----
    u32 tk;
    if (lane == 0) tk = atomicAdd(&g_ticket, 1u);
    tk = __shfl_sync(0xFFFFFFFFu, tk, 0);

    while (tk < (u32)ntiles) {
        const int base_b = (int)tk * 16;

        // monomial factors for this lane's two fragment rows (g, g+8):
        // m1 kept in rank-1 factor form (a01, a23) to save registers.
        float a01r[2][4], a23r[2][4], m2r[2][4];
        #pragma unroll
        for (int r = 0; r < 2; r++) {
            int brow = base_b + g + r * 8;
            const float4* xp = reinterpret_cast<const float4*>(X + (size_t)brow * 16);
            float4 x0 = xp[0], x1 = xp[1], x2 = xp[2], x3 = xp[3];

            a01r[r][0]=x0.x*x0.z; a01r[r][1]=x0.x*x0.w;
            a01r[r][2]=x0.y*x0.z; a01r[r][3]=x0.y*x0.w;
            a23r[r][0]=x1.x*x1.z; a23r[r][1]=x1.x*x1.w;
            a23r[r][2]=x1.y*x1.z; a23r[r][3]=x1.y*x1.w;

            float a45[4], a67[4];
            a45[0]=x2.x*x2.z; a45[1]=x2.x*x2.w; a45[2]=x2.y*x2.z; a45[3]=x2.y*x2.w;
            a67[0]=x3.x*x3.z; a67[1]=x3.x*x3.w; a67[2]=x3.y*x3.z; a67[3]=x3.y*x3.w;

            #pragma unroll
            for (int j = 0; j < 4; j++) {
                int a2 = 2 * tig + (j >> 1) * 8 + (j & 1);
                m2r[r][j] = a45[a2 >> 2] * a67[a2 & 3];
            }
        }

        float acc[4][4];
        #pragma unroll
        for (int n = 0; n < 4; n++)
            #pragma unroll
            for (int i = 0; i < 4; i++) acc[n][i] = 0.f;

        // ---- 16 K-chunks (each = one 'a' index) ----
        #pragma unroll
        for (int ks = 0; ks < 16; ks++) {
            float m10 = a01r[0][ks >> 2] * a23r[0][ks & 3];
            float m11 = a01r[1][ks >> 2] * a23r[1][ks & 3];

            float z00 = m10 * m2r[0][0], z01 = m10 * m2r[0][1];
            float z02 = m10 * m2r[0][2], z03 = m10 * m2r[0][3];
            float z10 = m11 * m2r[1][0], z11 = m11 * m2r[1][1];
            float z12 = m11 * m2r[1][2], z13 = m11 * m2r[1][3];

            u32 ah[4], al_[4];
            ah[0] = pack_hi(z00, z01);
            ah[1] = pack_hi(z10, z11);
            ah[2] = pack_hi(z02, z03);
            ah[3] = pack_hi(z12, z13);
            al_[0] = pack_lo_rn(z00 - trunc_bf(z00), z01 - trunc_bf(z01));
            al_[1] = pack_lo_rn(z10 - trunc_bf(z10), z11 - trunc_bf(z11));
            al_[2] = pack_lo_rn(z02 - trunc_bf(z02), z03 - trunc_bf(z03));
            al_[3] = pack_lo_rn(z12 - trunc_bf(z12), z13 - trunc_bf(z13));

            u32 bh0[4], bh1[4], bl0[4], bl1[4];
            #pragma unroll
            for (int n = 0; n < 4; n++) {
                ulonglong2 bp = sB[(ks * 4 + n) * 32 + lane];   // one LDS.128
                bh0[n] = (u32)bp.x; bh1[n] = (u32)(bp.x >> 32);
                bl0[n] = (u32)bp.y; bl1[n] = (u32)(bp.y >> 32);
            }

            #pragma unroll
            for (int n = 0; n < 4; n++) mma_bf16(acc[n], ah,  bh0[n], bh1[n]);
            #pragma unroll
            for (int n = 0; n < 4; n++) mma_bf16(acc[n], ah,  bl0[n], bl1[n]);
            #pragma unroll
            for (int n = 0; n < 4; n++) mma_bf16(acc[n], al_, bh0[n], bh1[n]);
        }

        // ---- epilogue: D frag rows g/g+8, cols n*8 + tig*2, +1 ----
        #pragma unroll
        for (int n = 0; n < 4; n++) {
            float2 v0; v0.x = acc[n][0]; v0.y = acc[n][1];
            float2 v1; v1.x = acc[n][2]; v1.y = acc[n][3];
            *reinterpret_cast<float2*>(out + (size_t)(base_b + g)     * 32 + n * 8 + tig * 2) = v0;
            *reinterpret_cast<float2*>(out + (size_t)(base_b + g + 8) * 32 + n * 8 + tig * 2) = v1;
        }

        if (lane == 0) tk = atomicAdd(&g_ticket, 1u);
        tk = __shfl_sync(0xFFFFFFFFu, tk, 0);
    }
}

// ---------------------------------------------------------------------------
extern "C" void kernel_launch(void* const* d_in, const int* in_sizes, int n_in,
                              void* d_out, int out_size)
{
    const float* X   = (const float*)d_in[0];
    const float* c11 = (const float*)d_in[1];
    const float* c12 = (const float*)d_in[2];
    const float* c13 = (const float*)d_in[3];
    const float* c14 = (const float*)d_in[4];
    const float* c21 = (const float*)d_in[5];
    const float* c22 = (const float*)d_in[6];
    const float* FM  = (const float*)d_in[7];
    const float* MT  = (const float*)d_in[8];
    (void)n_in; (void)out_size;

    int B = in_sizes[0] / 16;          // X is [B, 8, 2]
    int ntiles = B / 16;               // 4096 16-batch micro-tiles

    precompute_S<<<32, 256>>>(c11, c12, c13, c14, c21, c22, FM, MT);
    tree_main<<<296, 256>>>(X, (float*)d_out, ntiles);
}